// round 8
// baseline (speedup 1.0000x reference)
#include <cuda_runtime.h>
#include <math.h>

// ---------------------------------------------------------------------------
// Problem constants
// ---------------------------------------------------------------------------
#define T_  1024
#define D_  768
#define H_  12
#define FF_ 3072
#define V_  8192
#define HD_ 64

// output layout: xt_new [T*D] | xe_new [T*D] | dict_weights [H*T*V] | loss [1]
#define OFF_XE   (T_*D_)
#define OFF_W    (2*T_*D_)
#define OFF_LOSS (2*T_*D_ + H_*T_*V_)

// ---------------------------------------------------------------------------
// Device scratch (allocation-free: __device__ globals)
// ---------------------------------------------------------------------------
__device__ __align__(16) float g_xnorm[T_*D_];
__device__ __align__(16) float g_qk[T_*2*D_];
__device__ __align__(16) float g_v[H_*T_*HD_];
__device__ __align__(16) float g_vT[H_*HD_*T_];
__device__ __align__(16) float g_scores[H_*T_*T_];          // 50 MB
__device__ __align__(16) float g_y[T_*D_];
__device__ __align__(16) float g_x2[T_*D_];
__device__ __align__(16) float g_h[T_*H_*FF_];              // 151 MB
__device__ __align__(16) float g_xpre[T_*D_];
__device__ __align__(16) float g_xhat[T_*D_];
__device__ __align__(16) float g_embT[H_*HD_*V_];           // 25 MB
__device__ __align__(16) float g_recon[T_*D_];
__device__ double g_lossPartial[256];

// ---------------------------------------------------------------------------
// Generic NT GEMM: C[m,n] = alpha * sum_k A[m,k]*B[n,k]  (+bias, +gelu)
// A: [M,K] rows lda ; B: [N,K] rows ldb ; C: [M,N] rows ldc ; batched over z.
// mode: 0 = alpha only, 1 = +bias, 2 = +bias then exact gelu
// ---------------------------------------------------------------------------
__device__ __forceinline__ float gelu_exact(float x) {
    return 0.5f * x * (1.0f + erff(x * 0.70710678118654752f));
}

template<int BM, int BN, int BK, int TM, int TN>
__global__ void __launch_bounds__((BM/TM)*(BN/TN))
gemm_nt(const float* __restrict__ A, const float* __restrict__ B,
        float* __restrict__ C, const float* __restrict__ bias,
        int K, int lda, int ldb, int ldc,
        long long sA, long long sB, long long sC, long long sBias,
        float alpha, int mode, int causal)
{
    static_assert(TN % 4 == 0 && BK % 4 == 0, "vec4 constraints");
    constexpr int THREADS = (BM/TM)*(BN/TN);

    const int m0 = blockIdx.y * BM;
    const int n0 = blockIdx.x * BN;
    if (causal && n0 > m0 + BM - 1) return;   // fully-masked block (scores GEMM)

    __shared__ float As[BK][BM + 4];
    __shared__ float Bs[BK][BN + 4];

    const int bz = blockIdx.z;
    A += bz * sA;  B += bz * sB;  C += bz * sC;
    if (mode >= 1) bias += bz * sBias;

    const int tid = threadIdx.x;
    const int tx  = tid % (BN/TN);
    const int ty  = tid / (BN/TN);

    float acc[TM][TN];
    #pragma unroll
    for (int i = 0; i < TM; i++)
        #pragma unroll
        for (int j = 0; j < TN; j++) acc[i][j] = 0.f;

    for (int k0 = 0; k0 < K; k0 += BK) {
        for (int l = tid; l < BM*BK/4; l += THREADS) {
            int r = l / (BK/4), q4 = l % (BK/4);
            const float4 v = *reinterpret_cast<const float4*>(
                A + (long long)(m0 + r) * lda + k0 + q4*4);
            As[q4*4+0][r] = v.x; As[q4*4+1][r] = v.y;
            As[q4*4+2][r] = v.z; As[q4*4+3][r] = v.w;
        }
        for (int l = tid; l < BN*BK/4; l += THREADS) {
            int r = l / (BK/4), q4 = l % (BK/4);
            const float4 v = *reinterpret_cast<const float4*>(
                B + (long long)(n0 + r) * ldb + k0 + q4*4);
            Bs[q4*4+0][r] = v.x; Bs[q4*4+1][r] = v.y;
            Bs[q4*4+2][r] = v.z; Bs[q4*4+3][r] = v.w;
        }
        __syncthreads();
        #pragma unroll
        for (int k = 0; k < BK; k++) {
            float a[TM], b[TN];
            #pragma unroll
            for (int i = 0; i < TM; i++) a[i] = As[k][ty*TM + i];
            #pragma unroll
            for (int j = 0; j < TN; j++) b[j] = Bs[k][tx*TN + j];
            #pragma unroll
            for (int i = 0; i < TM; i++)
                #pragma unroll
                for (int j = 0; j < TN; j++) acc[i][j] += a[i] * b[j];
        }
        __syncthreads();
    }

    #pragma unroll
    for (int i = 0; i < TM; i++) {
        const int m = m0 + ty*TM + i;
        #pragma unroll
        for (int j4 = 0; j4 < TN/4; j4++) {
            float4 r4;
            float* cp = C + (long long)m * ldc + n0 + tx*TN + j4*4;
            float t0 = acc[i][j4*4+0] * alpha;
            float t1 = acc[i][j4*4+1] * alpha;
            float t2 = acc[i][j4*4+2] * alpha;
            float t3 = acc[i][j4*4+3] * alpha;
            if (mode >= 1) {
                const float* bp = bias + n0 + tx*TN + j4*4;
                t0 += bp[0]; t1 += bp[1]; t2 += bp[2]; t3 += bp[3];
            }
            if (mode == 2) {
                t0 = gelu_exact(t0); t1 = gelu_exact(t1);
                t2 = gelu_exact(t2); t3 = gelu_exact(t3);
            }
            r4.x = t0; r4.y = t1; r4.z = t2; r4.w = t3;
            *reinterpret_cast<float4*>(cp) = r4;
        }
    }
}

// ---------------------------------------------------------------------------
// LayerNorm over D=768 of (a + b)
// ---------------------------------------------------------------------------
__global__ void ln2in_kernel(const float* __restrict__ a, const float* __restrict__ b,
                             const float* __restrict__ w, const float* __restrict__ bb,
                             float* __restrict__ out)
{
    const int t = blockIdx.x;
    const int tid = threadIdx.x;
    const float* pa = a + (long long)t * D_;
    const float* pb = b + (long long)t * D_;
    float x[3];
    float s = 0.f, ss = 0.f;
    #pragma unroll
    for (int i = 0; i < 3; i++) {
        int d = tid + i*256;
        float v = pa[d] + pb[d];
        x[i] = v; s += v; ss += v*v;
    }
    #pragma unroll
    for (int o = 16; o; o >>= 1) {
        s  += __shfl_xor_sync(0xffffffffu, s, o);
        ss += __shfl_xor_sync(0xffffffffu, ss, o);
    }
    __shared__ float rs[8], rss[8];
    __shared__ float s_mu, s_inv;
    if ((tid & 31) == 0) { rs[tid >> 5] = s; rss[tid >> 5] = ss; }
    __syncthreads();
    if (tid == 0) {
        float S = 0.f, SS = 0.f;
        #pragma unroll
        for (int i = 0; i < 8; i++) { S += rs[i]; SS += rss[i]; }
        float mu  = S * (1.f / D_);
        float var = SS * (1.f / D_) - mu*mu;
        s_mu = mu;
        s_inv = rsqrtf(var + 1e-5f);
    }
    __syncthreads();
    float mu = s_mu, inv = s_inv;
    #pragma unroll
    for (int i = 0; i < 3; i++) {
        int d = tid + i*256;
        out[(long long)t*D_ + d] = (x[i] - mu) * inv * w[d] + bb[d];
    }
}

// v[h,t,d] = sum_j v_fact[h,j] * xt[t, j*64+d]
__global__ void vmix_kernel(const float* __restrict__ xt, const float* __restrict__ vf,
                            float* __restrict__ v)
{
    int idx = blockIdx.x * 256 + threadIdx.x;      // H*T*HD
    int d = idx & (HD_-1);
    int t = (idx >> 6) & (T_-1);
    int h = idx >> 16;
    float s = 0.f;
    #pragma unroll
    for (int j = 0; j < H_; j++)
        s += vf[h*H_ + j] * xt[(long long)t*D_ + j*HD_ + d];
    v[idx] = s;
}

// batched transpose in[b][R][C] -> out[b][C][R]   (R,C multiples of 32)
__global__ void transpose_kernel(const float* __restrict__ in, float* __restrict__ out,
                                 int R, int Cc)
{
    __shared__ float tile[32][33];
    const long long boff = (long long)blockIdx.z * R * Cc;
    in += boff; out += boff;
    int c0 = blockIdx.x * 32, r0 = blockIdx.y * 32;
    int x = threadIdx.x, y = threadIdx.y;
    #pragma unroll
    for (int i = 0; i < 32; i += 8)
        tile[y+i][x] = in[(long long)(r0 + y + i) * Cc + c0 + x];
    __syncthreads();
    #pragma unroll
    for (int i = 0; i < 32; i += 8)
        out[(long long)(c0 + y + i) * R + r0 + x] = tile[x][y+i];
}

// causal ALiBi softmax, in place on scores[h][i][:]
__global__ void attn_softmax_kernel(float* __restrict__ sc)
{
    const int bx = blockIdx.x;
    const int i = bx & (T_-1);
    const int h = bx >> 10;
    const float slope = (h < 8) ? exp2f(-(float)(h+1)) : exp2f(-0.5f * (float)(h-7));
    float* row = sc + ((long long)h*T_ + i) * T_;
    const int n = i + 1;
    const int tid = threadIdx.x;
    __shared__ float sh[8];

    float m = -3.4e38f;
    for (int j = tid; j < n; j += 256)
        m = fmaxf(m, row[j] + slope * (float)(j - i));
    #pragma unroll
    for (int o = 16; o; o >>= 1) m = fmaxf(m, __shfl_xor_sync(0xffffffffu, m, o));
    if ((tid & 31) == 0) sh[tid >> 5] = m;
    __syncthreads();
    float M = sh[0];
    #pragma unroll
    for (int w = 1; w < 8; w++) M = fmaxf(M, sh[w]);
    __syncthreads();

    float s = 0.f;
    for (int j = tid; j < n; j += 256) {
        float e = expf(row[j] + slope * (float)(j - i) - M);
        row[j] = e; s += e;
    }
    #pragma unroll
    for (int o = 16; o; o >>= 1) s += __shfl_xor_sync(0xffffffffu, s, o);
    if ((tid & 31) == 0) sh[tid >> 5] = s;
    __syncthreads();
    float S = 0.f;
    #pragma unroll
    for (int w = 0; w < 8; w++) S += sh[w];
    float inv = 1.f / S;
    for (int j = tid; j < n; j += 256) row[j] *= inv;
    for (int j = n + tid; j < T_; j += 256) row[j] = 0.f;
}

// xt_new[t, i*64+d] = xt + sum_j out_fact[i,j] * y[t, j*64+d]
__global__ void outmix_kernel(const float* __restrict__ xt, const float* __restrict__ of,
                              const float* __restrict__ y, float* __restrict__ o)
{
    int idx = blockIdx.x * 256 + threadIdx.x;      // T*D
    int d = idx & (HD_-1);
    int i = (idx >> 6) % H_;
    int t = idx / D_;
    float s = 0.f;
    #pragma unroll
    for (int j = 0; j < H_; j++)
        s += of[i*H_ + j] * y[(long long)t*D_ + j*HD_ + d];
    o[idx] = xt[idx] + s;
}

// per-(h,t) LayerNorm over HD=64 (one warp per row)
__global__ void dln_kernel(const float* __restrict__ xp, const float* __restrict__ w,
                           const float* __restrict__ b, float* __restrict__ xh)
{
    int bx = blockIdx.x;
    int t = bx & (T_-1);
    int h = bx >> 10;
    int lane = threadIdx.x;
    const float* p = xp + (long long)t*D_ + h*HD_;
    float v0 = p[lane], v1 = p[lane + 32];
    float s = v0 + v1, ss = v0*v0 + v1*v1;
    #pragma unroll
    for (int o = 16; o; o >>= 1) {
        s  += __shfl_xor_sync(0xffffffffu, s, o);
        ss += __shfl_xor_sync(0xffffffffu, ss, o);
    }
    float mu  = s * (1.f / HD_);
    float var = ss * (1.f / HD_) - mu*mu;
    float inv = rsqrtf(var + 1e-5f);
    float* q = xh + (long long)t*D_ + h*HD_;
    q[lane]      = (v0 - mu) * inv * w[h*HD_ + lane]      + b[h*HD_ + lane];
    q[lane + 32] = (v1 - mu) * inv * w[h*HD_ + lane + 32] + b[h*HD_ + lane + 32];
}

// softmax over V=8192, in place (row held in registers: 8 float4 / thread)
__global__ void dict_softmax_kernel(float* __restrict__ wts)
{
    float4* row = reinterpret_cast<float4*>(wts + (long long)blockIdx.x * V_);
    const int tid = threadIdx.x;
    __shared__ float sh[8];
    float4 v[8];
    float m = -3.4e38f;
    #pragma unroll
    for (int i = 0; i < 8; i++) {
        v[i] = row[tid + i*256];
        m = fmaxf(m, fmaxf(fmaxf(v[i].x, v[i].y), fmaxf(v[i].z, v[i].w)));
    }
    #pragma unroll
    for (int o = 16; o; o >>= 1) m = fmaxf(m, __shfl_xor_sync(0xffffffffu, m, o));
    if ((tid & 31) == 0) sh[tid >> 5] = m;
    __syncthreads();
    float M = sh[0];
    #pragma unroll
    for (int w = 1; w < 8; w++) M = fmaxf(M, sh[w]);
    __syncthreads();

    float s = 0.f;
    #pragma unroll
    for (int i = 0; i < 8; i++) {
        v[i].x = expf(v[i].x - M); v[i].y = expf(v[i].y - M);
        v[i].z = expf(v[i].z - M); v[i].w = expf(v[i].w - M);
        s += v[i].x + v[i].y + v[i].z + v[i].w;
    }
    #pragma unroll
    for (int o = 16; o; o >>= 1) s += __shfl_xor_sync(0xffffffffu, s, o);
    if ((tid & 31) == 0) sh[tid >> 5] = s;
    __syncthreads();
    float S = 0.f;
    #pragma unroll
    for (int w = 0; w < 8; w++) S += sh[w];
    float inv = 1.f / S;
    #pragma unroll
    for (int i = 0; i < 8; i++) {
        v[i].x *= inv; v[i].y *= inv; v[i].z *= inv; v[i].w *= inv;
        row[tid + i*256] = v[i];
    }
}

__global__ void add_kernel(const float* __restrict__ a, const float* __restrict__ b,
                           float* __restrict__ o)
{
    int idx = blockIdx.x * 256 + threadIdx.x;
    o[idx] = a[idx] + b[idx];
}

__global__ void loss_partial_kernel(const float* __restrict__ a, const float* __restrict__ b)
{
    double s = 0.0;
    for (int idx = blockIdx.x*256 + threadIdx.x; idx < T_*D_; idx += 256*256) {
        float d = a[idx] - b[idx];
        s += (double)d * (double)d;
    }
    __shared__ double sh[256];
    sh[threadIdx.x] = s;
    __syncthreads();
    for (int o = 128; o; o >>= 1) {
        if (threadIdx.x < o) sh[threadIdx.x] += sh[threadIdx.x + o];
        __syncthreads();
    }
    if (threadIdx.x == 0) g_lossPartial[blockIdx.x] = sh[0];
}

__global__ void loss_final_kernel(float* __restrict__ out)
{
    __shared__ double sh[256];
    sh[threadIdx.x] = g_lossPartial[threadIdx.x];
    __syncthreads();
    for (int o = 128; o; o >>= 1) {
        if (threadIdx.x < o) sh[threadIdx.x] += sh[threadIdx.x + o];
        __syncthreads();
    }
    if (threadIdx.x == 0) out[0] = (float)(sh[0] / (double)(T_*D_));
}

// ---------------------------------------------------------------------------
// Host launcher
// ---------------------------------------------------------------------------
extern "C" void kernel_launch(void* const* d_in, const int* in_sizes, int n_in,
                              void* d_out, int out_size)
{
    (void)in_sizes; (void)n_in; (void)out_size;
    const float* xt       = (const float*)d_in[0];
    const float* xe       = (const float*)d_in[1];
    const float* ln1_w    = (const float*)d_in[2];
    const float* ln1_b    = (const float*)d_in[3];
    const float* qk_w     = (const float*)d_in[4];
    const float* qk_b     = (const float*)d_in[5];
    const float* v_fact   = (const float*)d_in[6];
    const float* out_fact = (const float*)d_in[7];
    const float* ln2_w    = (const float*)d_in[8];
    const float* ln2_b    = (const float*)d_in[9];
    const float* fc_w     = (const float*)d_in[10];
    const float* fc_b     = (const float*)d_in[11];
    const float* proj_w   = (const float*)d_in[12];
    const float* proj_b   = (const float*)d_in[13];
    const float* dln_w    = (const float*)d_in[14];
    const float* dln_b    = (const float*)d_in[15];
    const float* dict_emb = (const float*)d_in[16];

    float* out    = (float*)d_out;
    float* o_xt   = out;
    float* o_xe   = out + OFF_XE;
    float* o_w    = out + OFF_W;
    float* o_loss = out + OFF_LOSS;

    float *p_xnorm, *p_qk, *p_v, *p_vT, *p_sc, *p_y, *p_x2, *p_h,
          *p_xpre, *p_xhat, *p_embT, *p_recon;
    cudaGetSymbolAddress((void**)&p_xnorm, g_xnorm);
    cudaGetSymbolAddress((void**)&p_qk,    g_qk);
    cudaGetSymbolAddress((void**)&p_v,     g_v);
    cudaGetSymbolAddress((void**)&p_vT,    g_vT);
    cudaGetSymbolAddress((void**)&p_sc,    g_scores);
    cudaGetSymbolAddress((void**)&p_y,     g_y);
    cudaGetSymbolAddress((void**)&p_x2,    g_x2);
    cudaGetSymbolAddress((void**)&p_h,     g_h);
    cudaGetSymbolAddress((void**)&p_xpre,  g_xpre);
    cudaGetSymbolAddress((void**)&p_xhat,  g_xhat);
    cudaGetSymbolAddress((void**)&p_embT,  g_embT);
    cudaGetSymbolAddress((void**)&p_recon, g_recon);

    // 1) x_norm = LN(xt + xe)
    ln2in_kernel<<<T_, 256>>>(xt, xe, ln1_w, ln1_b, p_xnorm);

    // 2) qk = x_norm @ qk_w^T + qk_b       [T, 1536]
    gemm_nt<128,128,16,8,8><<<dim3(2*D_/128, T_/128, 1), 256>>>(
        p_xnorm, qk_w, p_qk, qk_b, D_, D_, D_, 2*D_, 0,0,0,0, 1.f, 1, 0);

    // 3) v[h,t,d] then vT[h,d,t]
    vmix_kernel<<<H_*T_*HD_/256, 256>>>(xt, v_fact, p_v);
    transpose_kernel<<<dim3(HD_/32, T_/32, H_), dim3(32,8)>>>(p_v, p_vT, T_, HD_);

    // 4) scores[h] = 0.125 * q[h] @ k[h]^T   (causal blocks only)
    gemm_nt<128,128,16,8,8><<<dim3(T_/128, T_/128, H_), 256>>>(
        p_qk, p_qk + D_, p_sc, nullptr, HD_, 2*D_, 2*D_, T_,
        64, 64, (long long)T_*T_, 0, 0.125f, 0, 1);

    // 5) causal ALiBi softmax in place
    attn_softmax_kernel<<<H_*T_, 256>>>(p_sc);

    // 6) y[h] = probs[h] @ v[h]  -> g_y[t, h*64+d]
    gemm_nt<64,64,16,4,4><<<dim3(HD_/64, T_/64, H_), 256>>>(
        p_sc, p_vT, p_y, nullptr, T_, T_, T_, D_,
        (long long)T_*T_, (long long)HD_*T_, 64, 0, 1.f, 0, 0);

    // 7) xt_new = xt + out_fact-mix(y)   (output region 0)
    outmix_kernel<<<T_*D_/256, 256>>>(xt, out_fact, p_y, o_xt);

    // 8) x2 = LN(xt_new + xe)
    ln2in_kernel<<<T_, 256>>>(o_xt, xe, ln2_w, ln2_b, p_x2);

    // 9) h = gelu(x2 @ fc_w^T + fc_b)   [T, H*FF]   -- dominant GEMM
    gemm_nt<128,128,16,8,8><<<dim3(H_*FF_/128, T_/128, 1), 256>>>(
        p_x2, fc_w, p_h, fc_b, D_, D_, D_, H_*FF_, 0,0,0,0, 1.f, 2, 0);

    // 10) xpre[h] = h[h] @ proj_w[h]^T + proj_b[h]  -> [t, h*64+d]
    gemm_nt<64,64,16,4,4><<<dim3(HD_/64, T_/64, H_), 256>>>(
        p_h, proj_w, p_xpre, proj_b, FF_, H_*FF_, FF_, D_,
        FF_, (long long)HD_*FF_, 64, HD_, 1.f, 1, 0);

    // 11) x_hat = per-head LN(xpre)
    dln_kernel<<<H_*T_, 32>>>(p_xpre, dln_w, dln_b, p_xhat);

    // 12) embT[h] = dict_emb[h]^T    [HD, V]
    transpose_kernel<<<dim3(HD_/32, V_/32, H_), dim3(32,8)>>>(dict_emb, p_embT, V_, HD_);

    // 13) dict_logits[h] = x_hat[h] @ dict_emb[h]^T  -> output region (in place softmax next)
    gemm_nt<128,128,16,8,8><<<dim3(V_/128, T_/128, H_), 256>>>(
        p_xhat, dict_emb, o_w, nullptr, HD_, D_, HD_, V_,
        64, (long long)V_*HD_, (long long)T_*V_, 0, 1.f, 0, 0);

    // 14) dict_weights = softmax over V (in place in output)
    dict_softmax_kernel<<<H_*T_, 256>>>(o_w);

    // 15) x_recon[h] = weights[h] @ dict_emb[h]  -> [t, h*64+d]
    gemm_nt<64,64,16,4,4><<<dim3(HD_/64, T_/64, H_), 256>>>(
        o_w, p_embT, p_recon, nullptr, V_, V_, V_, D_,
        (long long)T_*V_, (long long)HD_*V_, 64, 0, 1.f, 0, 0);

    // 16) xe_new = xe + x_recon
    add_kernel<<<T_*D_/256, 256>>>(xe, p_recon, o_xe);

    // 17) dict_loss = mean((x_hat - x_recon)^2)
    loss_partial_kernel<<<256, 256>>>(p_xhat, p_recon);
    loss_final_kernel<<<1, 256>>>(o_loss);
}

// round 9
// speedup vs baseline: 1.0006x; 1.0006x over previous
#include <cuda_runtime.h>
#include <math.h>

// ---------------------------------------------------------------------------
// Problem constants
// ---------------------------------------------------------------------------
#define T_  1024
#define D_  768
#define H_  12
#define FF_ 3072
#define V_  8192
#define HD_ 64

// output layout: xt_new [T*D] | xe_new [T*D] | dict_weights [H*T*V] | loss [1]
#define OFF_XE   (T_*D_)
#define OFF_W    (2*T_*D_)
#define OFF_LOSS (2*T_*D_ + H_*T_*V_)

// ---------------------------------------------------------------------------
// Device scratch (allocation-free: __device__ globals)
// ---------------------------------------------------------------------------
__device__ __align__(16) float g_xnorm[T_*D_];
__device__ __align__(16) float g_qk[T_*2*D_];
__device__ __align__(16) float g_v[H_*T_*HD_];
__device__ __align__(16) float g_vT[H_*HD_*T_];
__device__ __align__(16) float g_scores[H_*T_*T_];          // 50 MB
__device__ __align__(16) float g_y[T_*D_];
__device__ __align__(16) float g_x2[T_*D_];
__device__ __align__(16) float g_h[T_*H_*FF_];              // 151 MB
__device__ __align__(16) float g_xpre[T_*D_];
__device__ __align__(16) float g_xhat[T_*D_];
__device__ __align__(16) float g_embT[H_*HD_*V_];           // 25 MB
__device__ __align__(16) float g_recon[T_*D_];
__device__ double g_lossPartial[256];

// ---------------------------------------------------------------------------
// Generic NT GEMM: C[m,n] = alpha * sum_k A[m,k]*B[n,k]  (+bias, +gelu)
// A: [M,K] rows lda ; B: [N,K] rows ldb ; C: [M,N] rows ldc ; batched over z.
// mode: 0 = alpha only, 1 = +bias, 2 = +bias then exact gelu
// ---------------------------------------------------------------------------
__device__ __forceinline__ float gelu_exact(float x) {
    return 0.5f * x * (1.0f + erff(x * 0.70710678118654752f));
}

template<int BM, int BN, int BK, int TM, int TN>
__global__ void __launch_bounds__((BM/TM)*(BN/TN))
gemm_nt(const float* __restrict__ A, const float* __restrict__ B,
        float* __restrict__ C, const float* __restrict__ bias,
        int K, int lda, int ldb, int ldc,
        long long sA, long long sB, long long sC, long long sBias,
        float alpha, int mode, int causal)
{
    static_assert(TN % 4 == 0 && BK % 4 == 0, "vec4 constraints");
    constexpr int THREADS = (BM/TM)*(BN/TN);

    const int m0 = blockIdx.y * BM;
    const int n0 = blockIdx.x * BN;
    if (causal && n0 > m0 + BM - 1) return;   // fully-masked block (scores GEMM)

    __shared__ float As[BK][BM + 4];
    __shared__ float Bs[BK][BN + 4];

    const int bz = blockIdx.z;
    A += bz * sA;  B += bz * sB;  C += bz * sC;
    if (mode >= 1) bias += bz * sBias;

    const int tid = threadIdx.x;
    const int tx  = tid % (BN/TN);
    const int ty  = tid / (BN/TN);

    float acc[TM][TN];
    #pragma unroll
    for (int i = 0; i < TM; i++)
        #pragma unroll
        for (int j = 0; j < TN; j++) acc[i][j] = 0.f;

    for (int k0 = 0; k0 < K; k0 += BK) {
        for (int l = tid; l < BM*BK/4; l += THREADS) {
            int r = l / (BK/4), q4 = l % (BK/4);
            const float4 v = *reinterpret_cast<const float4*>(
                A + (long long)(m0 + r) * lda + k0 + q4*4);
            As[q4*4+0][r] = v.x; As[q4*4+1][r] = v.y;
            As[q4*4+2][r] = v.z; As[q4*4+3][r] = v.w;
        }
        for (int l = tid; l < BN*BK/4; l += THREADS) {
            int r = l / (BK/4), q4 = l % (BK/4);
            const float4 v = *reinterpret_cast<const float4*>(
                B + (long long)(n0 + r) * ldb + k0 + q4*4);
            Bs[q4*4+0][r] = v.x; Bs[q4*4+1][r] = v.y;
            Bs[q4*4+2][r] = v.z; Bs[q4*4+3][r] = v.w;
        }
        __syncthreads();
        #pragma unroll
        for (int k = 0; k < BK; k++) {
            float a[TM], b[TN];
            #pragma unroll
            for (int i = 0; i < TM; i++) a[i] = As[k][ty*TM + i];
            #pragma unroll
            for (int j = 0; j < TN; j++) b[j] = Bs[k][tx*TN + j];
            #pragma unroll
            for (int i = 0; i < TM; i++)
                #pragma unroll
                for (int j = 0; j < TN; j++) acc[i][j] += a[i] * b[j];
        }
        __syncthreads();
    }

    #pragma unroll
    for (int i = 0; i < TM; i++) {
        const int m = m0 + ty*TM + i;
        #pragma unroll
        for (int j4 = 0; j4 < TN/4; j4++) {
            float4 r4;
            float* cp = C + (long long)m * ldc + n0 + tx*TN + j4*4;
            float t0 = acc[i][j4*4+0] * alpha;
            float t1 = acc[i][j4*4+1] * alpha;
            float t2 = acc[i][j4*4+2] * alpha;
            float t3 = acc[i][j4*4+3] * alpha;
            if (mode >= 1) {
                const float* bp = bias + n0 + tx*TN + j4*4;
                t0 += bp[0]; t1 += bp[1]; t2 += bp[2]; t3 += bp[3];
            }
            if (mode == 2) {
                t0 = gelu_exact(t0); t1 = gelu_exact(t1);
                t2 = gelu_exact(t2); t3 = gelu_exact(t3);
            }
            r4.x = t0; r4.y = t1; r4.z = t2; r4.w = t3;
            *reinterpret_cast<float4*>(cp) = r4;
        }
    }
}

// ---------------------------------------------------------------------------
// LayerNorm over D=768 of (a + b)
// ---------------------------------------------------------------------------
__global__ void ln2in_kernel(const float* __restrict__ a, const float* __restrict__ b,
                             const float* __restrict__ w, const float* __restrict__ bb,
                             float* __restrict__ out)
{
    const int t = blockIdx.x;
    const int tid = threadIdx.x;
    const float* pa = a + (long long)t * D_;
    const float* pb = b + (long long)t * D_;
    float x[3];
    float s = 0.f, ss = 0.f;
    #pragma unroll
    for (int i = 0; i < 3; i++) {
        int d = tid + i*256;
        float v = pa[d] + pb[d];
        x[i] = v; s += v; ss += v*v;
    }
    #pragma unroll
    for (int o = 16; o; o >>= 1) {
        s  += __shfl_xor_sync(0xffffffffu, s, o);
        ss += __shfl_xor_sync(0xffffffffu, ss, o);
    }
    __shared__ float rs[8], rss[8];
    __shared__ float s_mu, s_inv;
    if ((tid & 31) == 0) { rs[tid >> 5] = s; rss[tid >> 5] = ss; }
    __syncthreads();
    if (tid == 0) {
        float S = 0.f, SS = 0.f;
        #pragma unroll
        for (int i = 0; i < 8; i++) { S += rs[i]; SS += rss[i]; }
        float mu  = S * (1.f / D_);
        float var = SS * (1.f / D_) - mu*mu;
        s_mu = mu;
        s_inv = rsqrtf(var + 1e-5f);
    }
    __syncthreads();
    float mu = s_mu, inv = s_inv;
    #pragma unroll
    for (int i = 0; i < 3; i++) {
        int d = tid + i*256;
        out[(long long)t*D_ + d] = (x[i] - mu) * inv * w[d] + bb[d];
    }
}

// v[h,t,d] = sum_j v_fact[h,j] * xt[t, j*64+d]
__global__ void vmix_kernel(const float* __restrict__ xt, const float* __restrict__ vf,
                            float* __restrict__ v)
{
    int idx = blockIdx.x * 256 + threadIdx.x;      // H*T*HD
    int d = idx & (HD_-1);
    int t = (idx >> 6) & (T_-1);
    int h = idx >> 16;
    float s = 0.f;
    #pragma unroll
    for (int j = 0; j < H_; j++)
        s += vf[h*H_ + j] * xt[(long long)t*D_ + j*HD_ + d];
    v[idx] = s;
}

// batched transpose in[b][R][C] -> out[b][C][R]   (R,C multiples of 32)
__global__ void transpose_kernel(const float* __restrict__ in, float* __restrict__ out,
                                 int R, int Cc)
{
    __shared__ float tile[32][33];
    const long long boff = (long long)blockIdx.z * R * Cc;
    in += boff; out += boff;
    int c0 = blockIdx.x * 32, r0 = blockIdx.y * 32;
    int x = threadIdx.x, y = threadIdx.y;
    #pragma unroll
    for (int i = 0; i < 32; i += 8)
        tile[y+i][x] = in[(long long)(r0 + y + i) * Cc + c0 + x];
    __syncthreads();
    #pragma unroll
    for (int i = 0; i < 32; i += 8)
        out[(long long)(c0 + y + i) * R + r0 + x] = tile[x][y+i];
}

// causal ALiBi softmax, in place on scores[h][i][:]
__global__ void attn_softmax_kernel(float* __restrict__ sc)
{
    const int bx = blockIdx.x;
    const int i = bx & (T_-1);
    const int h = bx >> 10;
    const float slope = (h < 8) ? exp2f(-(float)(h+1)) : exp2f(-0.5f * (float)(h-7));
    float* row = sc + ((long long)h*T_ + i) * T_;
    const int n = i + 1;
    const int tid = threadIdx.x;
    __shared__ float sh[8];

    float m = -3.4e38f;
    for (int j = tid; j < n; j += 256)
        m = fmaxf(m, row[j] + slope * (float)(j - i));
    #pragma unroll
    for (int o = 16; o; o >>= 1) m = fmaxf(m, __shfl_xor_sync(0xffffffffu, m, o));
    if ((tid & 31) == 0) sh[tid >> 5] = m;
    __syncthreads();
    float M = sh[0];
    #pragma unroll
    for (int w = 1; w < 8; w++) M = fmaxf(M, sh[w]);
    __syncthreads();

    float s = 0.f;
    for (int j = tid; j < n; j += 256) {
        float e = expf(row[j] + slope * (float)(j - i) - M);
        row[j] = e; s += e;
    }
    #pragma unroll
    for (int o = 16; o; o >>= 1) s += __shfl_xor_sync(0xffffffffu, s, o);
    if ((tid & 31) == 0) sh[tid >> 5] = s;
    __syncthreads();
    float S = 0.f;
    #pragma unroll
    for (int w = 0; w < 8; w++) S += sh[w];
    float inv = 1.f / S;
    for (int j = tid; j < n; j += 256) row[j] *= inv;
    for (int j = n + tid; j < T_; j += 256) row[j] = 0.f;
}

// xt_new[t, i*64+d] = xt + sum_j out_fact[i,j] * y[t, j*64+d]
__global__ void outmix_kernel(const float* __restrict__ xt, const float* __restrict__ of,
                              const float* __restrict__ y, float* __restrict__ o)
{
    int idx = blockIdx.x * 256 + threadIdx.x;      // T*D
    int d = idx & (HD_-1);
    int i = (idx >> 6) % H_;
    int t = idx / D_;
    float s = 0.f;
    #pragma unroll
    for (int j = 0; j < H_; j++)
        s += of[i*H_ + j] * y[(long long)t*D_ + j*HD_ + d];
    o[idx] = xt[idx] + s;
}

// per-(h,t) LayerNorm over HD=64 (one warp per row)
__global__ void dln_kernel(const float* __restrict__ xp, const float* __restrict__ w,
                           const float* __restrict__ b, float* __restrict__ xh)
{
    int bx = blockIdx.x;
    int t = bx & (T_-1);
    int h = bx >> 10;
    int lane = threadIdx.x;
    const float* p = xp + (long long)t*D_ + h*HD_;
    float v0 = p[lane], v1 = p[lane + 32];
    float s = v0 + v1, ss = v0*v0 + v1*v1;
    #pragma unroll
    for (int o = 16; o; o >>= 1) {
        s  += __shfl_xor_sync(0xffffffffu, s, o);
        ss += __shfl_xor_sync(0xffffffffu, ss, o);
    }
    float mu  = s * (1.f / HD_);
    float var = ss * (1.f / HD_) - mu*mu;
    float inv = rsqrtf(var + 1e-5f);
    float* q = xh + (long long)t*D_ + h*HD_;
    q[lane]      = (v0 - mu) * inv * w[h*HD_ + lane]      + b[h*HD_ + lane];
    q[lane + 32] = (v1 - mu) * inv * w[h*HD_ + lane + 32] + b[h*HD_ + lane + 32];
}

// softmax over V=8192, in place (row held in registers: 8 float4 / thread)
__global__ void dict_softmax_kernel(float* __restrict__ wts)
{
    float4* row = reinterpret_cast<float4*>(wts + (long long)blockIdx.x * V_);
    const int tid = threadIdx.x;
    __shared__ float sh[8];
    float4 v[8];
    float m = -3.4e38f;
    #pragma unroll
    for (int i = 0; i < 8; i++) {
        v[i] = row[tid + i*256];
        m = fmaxf(m, fmaxf(fmaxf(v[i].x, v[i].y), fmaxf(v[i].z, v[i].w)));
    }
    #pragma unroll
    for (int o = 16; o; o >>= 1) m = fmaxf(m, __shfl_xor_sync(0xffffffffu, m, o));
    if ((tid & 31) == 0) sh[tid >> 5] = m;
    __syncthreads();
    float M = sh[0];
    #pragma unroll
    for (int w = 1; w < 8; w++) M = fmaxf(M, sh[w]);
    __syncthreads();

    float s = 0.f;
    #pragma unroll
    for (int i = 0; i < 8; i++) {
        v[i].x = expf(v[i].x - M); v[i].y = expf(v[i].y - M);
        v[i].z = expf(v[i].z - M); v[i].w = expf(v[i].w - M);
        s += v[i].x + v[i].y + v[i].z + v[i].w;
    }
    #pragma unroll
    for (int o = 16; o; o >>= 1) s += __shfl_xor_sync(0xffffffffu, s, o);
    if ((tid & 31) == 0) sh[tid >> 5] = s;
    __syncthreads();
    float S = 0.f;
    #pragma unroll
    for (int w = 0; w < 8; w++) S += sh[w];
    float inv = 1.f / S;
    #pragma unroll
    for (int i = 0; i < 8; i++) {
        v[i].x *= inv; v[i].y *= inv; v[i].z *= inv; v[i].w *= inv;
        row[tid + i*256] = v[i];
    }
}

__global__ void add_kernel(const float* __restrict__ a, const float* __restrict__ b,
                           float* __restrict__ o)
{
    int idx = blockIdx.x * 256 + threadIdx.x;
    o[idx] = a[idx] + b[idx];
}

__global__ void loss_partial_kernel(const float* __restrict__ a, const float* __restrict__ b)
{
    double s = 0.0;
    for (int idx = blockIdx.x*256 + threadIdx.x; idx < T_*D_; idx += 256*256) {
        float d = a[idx] - b[idx];
        s += (double)d * (double)d;
    }
    __shared__ double sh[256];
    sh[threadIdx.x] = s;
    __syncthreads();
    for (int o = 128; o; o >>= 1) {
        if (threadIdx.x < o) sh[threadIdx.x] += sh[threadIdx.x + o];
        __syncthreads();
    }
    if (threadIdx.x == 0) g_lossPartial[blockIdx.x] = sh[0];
}

__global__ void loss_final_kernel(float* __restrict__ out)
{
    __shared__ double sh[256];
    sh[threadIdx.x] = g_lossPartial[threadIdx.x];
    __syncthreads();
    for (int o = 128; o; o >>= 1) {
        if (threadIdx.x < o) sh[threadIdx.x] += sh[threadIdx.x + o];
        __syncthreads();
    }
    if (threadIdx.x == 0) out[0] = (float)(sh[0] / (double)(T_*D_));
}

// ---------------------------------------------------------------------------
// Host launcher
// ---------------------------------------------------------------------------
extern "C" void kernel_launch(void* const* d_in, const int* in_sizes, int n_in,
                              void* d_out, int out_size)
{
    (void)in_sizes; (void)n_in; (void)out_size;
    const float* xt       = (const float*)d_in[0];
    const float* xe       = (const float*)d_in[1];
    const float* ln1_w    = (const float*)d_in[2];
    const float* ln1_b    = (const float*)d_in[3];
    const float* qk_w     = (const float*)d_in[4];
    const float* qk_b     = (const float*)d_in[5];
    const float* v_fact   = (const float*)d_in[6];
    const float* out_fact = (const float*)d_in[7];
    const float* ln2_w    = (const float*)d_in[8];
    const float* ln2_b    = (const float*)d_in[9];
    const float* fc_w     = (const float*)d_in[10];
    const float* fc_b     = (const float*)d_in[11];
    const float* proj_w   = (const float*)d_in[12];
    const float* proj_b   = (const float*)d_in[13];
    const float* dln_w    = (const float*)d_in[14];
    const float* dln_b    = (const float*)d_in[15];
    const float* dict_emb = (const float*)d_in[16];

    float* out    = (float*)d_out;
    float* o_xt   = out;
    float* o_xe   = out + OFF_XE;
    float* o_w    = out + OFF_W;
    float* o_loss = out + OFF_LOSS;

    float *p_xnorm, *p_qk, *p_v, *p_vT, *p_sc, *p_y, *p_x2, *p_h,
          *p_xpre, *p_xhat, *p_embT, *p_recon;
    cudaGetSymbolAddress((void**)&p_xnorm, g_xnorm);
    cudaGetSymbolAddress((void**)&p_qk,    g_qk);
    cudaGetSymbolAddress((void**)&p_v,     g_v);
    cudaGetSymbolAddress((void**)&p_vT,    g_vT);
    cudaGetSymbolAddress((void**)&p_sc,    g_scores);
    cudaGetSymbolAddress((void**)&p_y,     g_y);
    cudaGetSymbolAddress((void**)&p_x2,    g_x2);
    cudaGetSymbolAddress((void**)&p_h,     g_h);
    cudaGetSymbolAddress((void**)&p_xpre,  g_xpre);
    cudaGetSymbolAddress((void**)&p_xhat,  g_xhat);
    cudaGetSymbolAddress((void**)&p_embT,  g_embT);
    cudaGetSymbolAddress((void**)&p_recon, g_recon);

    // 1) x_norm = LN(xt + xe)
    ln2in_kernel<<<T_, 256>>>(xt, xe, ln1_w, ln1_b, p_xnorm);

    // 2) qk = x_norm @ qk_w^T + qk_b       [T, 1536]
    gemm_nt<128,128,16,8,8><<<dim3(2*D_/128, T_/128, 1), 256>>>(
        p_xnorm, qk_w, p_qk, qk_b, D_, D_, D_, 2*D_, 0,0,0,0, 1.f, 1, 0);

    // 3) v[h,t,d] then vT[h,d,t]
    vmix_kernel<<<H_*T_*HD_/256, 256>>>(xt, v_fact, p_v);
    transpose_kernel<<<dim3(HD_/32, T_/32, H_), dim3(32,8)>>>(p_v, p_vT, T_, HD_);

    // 4) scores[h] = 0.125 * q[h] @ k[h]^T   (causal blocks only)
    gemm_nt<128,128,16,8,8><<<dim3(T_/128, T_/128, H_), 256>>>(
        p_qk, p_qk + D_, p_sc, nullptr, HD_, 2*D_, 2*D_, T_,
        64, 64, (long long)T_*T_, 0, 0.125f, 0, 1);

    // 5) causal ALiBi softmax in place
    attn_softmax_kernel<<<H_*T_, 256>>>(p_sc);

    // 6) y[h] = probs[h] @ v[h]  -> g_y[t, h*64+d]
    gemm_nt<64,64,16,4,4><<<dim3(HD_/64, T_/64, H_), 256>>>(
        p_sc, p_vT, p_y, nullptr, T_, T_, T_, D_,
        (long long)T_*T_, (long long)HD_*T_, 64, 0, 1.f, 0, 0);

    // 7) xt_new = xt + out_fact-mix(y)   (output region 0)
    outmix_kernel<<<T_*D_/256, 256>>>(xt, out_fact, p_y, o_xt);

    // 8) x2 = LN(xt_new + xe)
    ln2in_kernel<<<T_, 256>>>(o_xt, xe, ln2_w, ln2_b, p_x2);

    // 9) h = gelu(x2 @ fc_w^T + fc_b)   [T, H*FF]   -- dominant GEMM
    gemm_nt<128,128,16,8,8><<<dim3(H_*FF_/128, T_/128, 1), 256>>>(
        p_x2, fc_w, p_h, fc_b, D_, D_, D_, H_*FF_, 0,0,0,0, 1.f, 2, 0);

    // 10) xpre[h] = h[h] @ proj_w[h]^T + proj_b[h]  -> [t, h*64+d]
    gemm_nt<64,64,16,4,4><<<dim3(HD_/64, T_/64, H_), 256>>>(
        p_h, proj_w, p_xpre, proj_b, FF_, H_*FF_, FF_, D_,
        FF_, (long long)HD_*FF_, 64, HD_, 1.f, 1, 0);

    // 11) x_hat = per-head LN(xpre)
    dln_kernel<<<H_*T_, 32>>>(p_xpre, dln_w, dln_b, p_xhat);

    // 12) embT[h] = dict_emb[h]^T    [HD, V]
    transpose_kernel<<<dim3(HD_/32, V_/32, H_), dim3(32,8)>>>(dict_emb, p_embT, V_, HD_);

    // 13) dict_logits[h] = x_hat[h] @ dict_emb[h]^T  -> output region (in place softmax next)
    gemm_nt<128,128,16,8,8><<<dim3(V_/128, T_/128, H_), 256>>>(
        p_xhat, dict_emb, o_w, nullptr, HD_, D_, HD_, V_,
        64, (long long)V_*HD_, (long long)T_*V_, 0, 1.f, 0, 0);

    // 14) dict_weights = softmax over V (in place in output)
    dict_softmax_kernel<<<H_*T_, 256>>>(o_w);

    // 15) x_recon[h] = weights[h] @ dict_emb[h]  -> [t, h*64+d]
    gemm_nt<64,64,16,4,4><<<dim3(HD_/64, T_/64, H_), 256>>>(
        o_w, p_embT, p_recon, nullptr, V_, V_, V_, D_,
        (long long)T_*V_, (long long)HD_*V_, 64, 0, 1.f, 0, 0);

    // 16) xe_new = xe + x_recon
    add_kernel<<<T_*D_/256, 256>>>(xe, p_recon, o_xe);

    // 17) dict_loss = mean((x_hat - x_recon)^2)
    loss_partial_kernel<<<256, 256>>>(p_xhat, p_recon);
    loss_final_kernel<<<1, 256>>>(o_loss);
}

// round 10
// speedup vs baseline: 2.4442x; 2.4426x over previous
#include <cuda_runtime.h>
#include <math.h>

// ---------------------------------------------------------------------------
// Problem constants
// ---------------------------------------------------------------------------
#define T_  1024
#define D_  768
#define H_  12
#define FF_ 3072
#define V_  8192
#define HD_ 64

// output layout: xt_new [T*D] | xe_new [T*D] | dict_weights [H*T*V] | loss [1]
#define OFF_XE   (T_*D_)
#define OFF_W    (2*T_*D_)
#define OFF_LOSS (2*T_*D_ + H_*T_*V_)

// ---------------------------------------------------------------------------
// Device scratch (allocation-free: __device__ globals)
// ---------------------------------------------------------------------------
__device__ __align__(16) float g_xnorm[T_*D_];
__device__ __align__(16) float g_qk[T_*2*D_];
__device__ __align__(16) float g_v[H_*T_*HD_];
__device__ __align__(16) float g_vT[H_*HD_*T_];
__device__ __align__(16) float g_scores[H_*T_*T_];          // 50 MB
__device__ __align__(16) float g_y[T_*D_];
__device__ __align__(16) float g_x2[T_*D_];
__device__ __align__(16) float g_h[T_*H_*FF_];              // 151 MB
__device__ __align__(16) float g_xpre[T_*D_];
__device__ __align__(16) float g_xhat[T_*D_];
__device__ __align__(16) float g_embT[H_*HD_*V_];           // 25 MB
__device__ __align__(16) float g_recon[T_*D_];
__device__ double g_lossPartial[256];

// ---------------------------------------------------------------------------
// Helpers
// ---------------------------------------------------------------------------
__device__ __forceinline__ float gelu_exact(float x) {
    return 0.5f * x * (1.0f + erff(x * 0.70710678118654752f));
}

__device__ __forceinline__ unsigned f2tf(float x) {
    unsigned r;
    asm("cvt.rna.tf32.f32 %0, %1;" : "=r"(r) : "f"(x));
    return r;
}

// ---------------------------------------------------------------------------
// Tensor-core NT GEMM (tf32 mma.sync m16n8k8):
//   C[m,n] = alpha * sum_k A[m,k]*B[n,k]   (+bias, +gelu) ; batched over z
// A: [M,K] rows lda ; B: [N,K] rows ldb ; C: [M,N] rows ldc.
// mode: 0 = alpha only, 1 = +bias, 2 = +bias then exact gelu
// causal: skip blocks fully above the diagonal (scores)
// kcap:   effective K = min(K, m0+BM)   (attn @ V: probs zero past diagonal)
// swapxy: take m-block from blockIdx.x (so same-B blocks are adjacent)
// ---------------------------------------------------------------------------
template<int BM, int BN, int BK, int WM, int WN, int THREADS>
__global__ void __launch_bounds__(THREADS)
gemm_tc(const float* __restrict__ A, const float* __restrict__ B,
        float* __restrict__ C, const float* __restrict__ bias,
        int K, int lda, int ldb, int ldc,
        long long sA, long long sB, long long sC, long long sBias,
        float alpha, int mode, int causal, int kcap, int swapxy)
{
    constexpr int NWN = BN / WN;          // warps along N
    constexpr int TM  = WM / 16;          // mma tiles per warp along M
    constexpr int TN  = WN / 8;           // mma tiles per warp along N
    constexpr int LK  = BK + 4;           // smem row stride (words); 36 -> conflict-free

    const int bx = blockIdx.x, by = blockIdx.y;
    const int m0 = (swapxy ? bx : by) * BM;
    const int n0 = (swapxy ? by : bx) * BN;
    if (causal && n0 > m0 + BM - 1) return;

    __shared__ __align__(16) unsigned As[BM][LK];
    __shared__ __align__(16) unsigned Bs[BN][LK];

    const int bz = blockIdx.z;
    A += bz * sA;  B += bz * sB;  C += bz * sC;
    if (mode >= 1) bias += bz * sBias;

    const int tid  = threadIdx.x;
    const int lane = tid & 31;
    const int warp = tid >> 5;
    const int gid  = lane >> 2;           // 0..7
    const int t4   = lane & 3;            // 0..3
    const int wm   = warp / NWN;
    const int wn   = warp % NWN;

    float acc[TM][TN][4];
    #pragma unroll
    for (int i = 0; i < TM; i++)
        #pragma unroll
        for (int j = 0; j < TN; j++) {
            acc[i][j][0] = 0.f; acc[i][j][1] = 0.f;
            acc[i][j][2] = 0.f; acc[i][j][3] = 0.f;
        }

    int Keff = K;
    if (kcap) { int ke = m0 + BM; if (ke < K) Keff = ke; }

    for (int k0 = 0; k0 < Keff; k0 += BK) {
        // ---- global -> shared (coalesced float4 loads, STS.128, tf32 cvt) ----
        #pragma unroll
        for (int l = tid; l < BM * (BK/4); l += THREADS) {
            int r = l / (BK/4);
            int q = (l % (BK/4)) * 4;
            float4 v = *reinterpret_cast<const float4*>(
                A + (long long)(m0 + r) * lda + k0 + q);
            uint4 u; u.x = f2tf(v.x); u.y = f2tf(v.y); u.z = f2tf(v.z); u.w = f2tf(v.w);
            *reinterpret_cast<uint4*>(&As[r][q]) = u;
        }
        #pragma unroll
        for (int l = tid; l < BN * (BK/4); l += THREADS) {
            int r = l / (BK/4);
            int q = (l % (BK/4)) * 4;
            float4 v = *reinterpret_cast<const float4*>(
                B + (long long)(n0 + r) * ldb + k0 + q);
            uint4 u; u.x = f2tf(v.x); u.y = f2tf(v.y); u.z = f2tf(v.z); u.w = f2tf(v.w);
            *reinterpret_cast<uint4*>(&Bs[r][q]) = u;
        }
        __syncthreads();

        #pragma unroll
        for (int kk = 0; kk < BK; kk += 8) {
            unsigned a[TM][4], b[TN][2];
            #pragma unroll
            for (int i = 0; i < TM; i++) {
                int r = wm * WM + i * 16 + gid;
                a[i][0] = As[r    ][kk + t4];
                a[i][1] = As[r + 8][kk + t4];
                a[i][2] = As[r    ][kk + t4 + 4];
                a[i][3] = As[r + 8][kk + t4 + 4];
            }
            #pragma unroll
            for (int j = 0; j < TN; j++) {
                int c = wn * WN + j * 8 + gid;
                b[j][0] = Bs[c][kk + t4];
                b[j][1] = Bs[c][kk + t4 + 4];
            }
            #pragma unroll
            for (int i = 0; i < TM; i++)
                #pragma unroll
                for (int j = 0; j < TN; j++) {
                    asm volatile(
                        "mma.sync.aligned.m16n8k8.row.col.f32.tf32.tf32.f32 "
                        "{%0,%1,%2,%3}, {%4,%5,%6,%7}, {%8,%9}, {%0,%1,%2,%3};\n"
                        : "+f"(acc[i][j][0]), "+f"(acc[i][j][1]),
                          "+f"(acc[i][j][2]), "+f"(acc[i][j][3])
                        : "r"(a[i][0]), "r"(a[i][1]), "r"(a[i][2]), "r"(a[i][3]),
                          "r"(b[j][0]), "r"(b[j][1]));
                }
        }
        __syncthreads();
    }

    // ---- epilogue ----
    #pragma unroll
    for (int i = 0; i < TM; i++) {
        const int m = m0 + wm * WM + i * 16 + gid;
        #pragma unroll
        for (int j = 0; j < TN; j++) {
            const int n = n0 + wn * WN + j * 8 + t4 * 2;
            float c0 = acc[i][j][0] * alpha, c1 = acc[i][j][1] * alpha;
            float c2 = acc[i][j][2] * alpha, c3 = acc[i][j][3] * alpha;
            if (mode >= 1) {
                float b0 = bias[n], b1 = bias[n + 1];
                c0 += b0; c1 += b1; c2 += b0; c3 += b1;
            }
            if (mode == 2) {
                c0 = gelu_exact(c0); c1 = gelu_exact(c1);
                c2 = gelu_exact(c2); c3 = gelu_exact(c3);
            }
            *reinterpret_cast<float2*>(C + (long long)m       * ldc + n) = make_float2(c0, c1);
            *reinterpret_cast<float2*>(C + (long long)(m + 8) * ldc + n) = make_float2(c2, c3);
        }
    }
}

// ---------------------------------------------------------------------------
// LayerNorm over D=768 of (a + b)
// ---------------------------------------------------------------------------
__global__ void ln2in_kernel(const float* __restrict__ a, const float* __restrict__ b,
                             const float* __restrict__ w, const float* __restrict__ bb,
                             float* __restrict__ out)
{
    const int t = blockIdx.x;
    const int tid = threadIdx.x;
    const float* pa = a + (long long)t * D_;
    const float* pb = b + (long long)t * D_;
    float x[3];
    float s = 0.f, ss = 0.f;
    #pragma unroll
    for (int i = 0; i < 3; i++) {
        int d = tid + i*256;
        float v = pa[d] + pb[d];
        x[i] = v; s += v; ss += v*v;
    }
    #pragma unroll
    for (int o = 16; o; o >>= 1) {
        s  += __shfl_xor_sync(0xffffffffu, s, o);
        ss += __shfl_xor_sync(0xffffffffu, ss, o);
    }
    __shared__ float rs[8], rss[8];
    __shared__ float s_mu, s_inv;
    if ((tid & 31) == 0) { rs[tid >> 5] = s; rss[tid >> 5] = ss; }
    __syncthreads();
    if (tid == 0) {
        float S = 0.f, SS = 0.f;
        #pragma unroll
        for (int i = 0; i < 8; i++) { S += rs[i]; SS += rss[i]; }
        float mu  = S * (1.f / D_);
        float var = SS * (1.f / D_) - mu*mu;
        s_mu = mu;
        s_inv = rsqrtf(var + 1e-5f);
    }
    __syncthreads();
    float mu = s_mu, inv = s_inv;
    #pragma unroll
    for (int i = 0; i < 3; i++) {
        int d = tid + i*256;
        out[(long long)t*D_ + d] = (x[i] - mu) * inv * w[d] + bb[d];
    }
}

// v[h,t,d] = sum_j v_fact[h,j] * xt[t, j*64+d]
__global__ void vmix_kernel(const float* __restrict__ xt, const float* __restrict__ vf,
                            float* __restrict__ v)
{
    int idx = blockIdx.x * 256 + threadIdx.x;      // H*T*HD
    int d = idx & (HD_-1);
    int t = (idx >> 6) & (T_-1);
    int h = idx >> 16;
    float s = 0.f;
    #pragma unroll
    for (int j = 0; j < H_; j++)
        s += vf[h*H_ + j] * xt[(long long)t*D_ + j*HD_ + d];
    v[idx] = s;
}

// batched transpose in[b][R][C] -> out[b][C][R]   (R,C multiples of 32)
__global__ void transpose_kernel(const float* __restrict__ in, float* __restrict__ out,
                                 int R, int Cc)
{
    __shared__ float tile[32][33];
    const long long boff = (long long)blockIdx.z * R * Cc;
    in += boff; out += boff;
    int c0 = blockIdx.x * 32, r0 = blockIdx.y * 32;
    int x = threadIdx.x, y = threadIdx.y;
    #pragma unroll
    for (int i = 0; i < 32; i += 8)
        tile[y+i][x] = in[(long long)(r0 + y + i) * Cc + c0 + x];
    __syncthreads();
    #pragma unroll
    for (int i = 0; i < 32; i += 8)
        out[(long long)(c0 + y + i) * R + r0 + x] = tile[x][y+i];
}

// causal ALiBi softmax, in place on scores[h][i][:]
__global__ void attn_softmax_kernel(float* __restrict__ sc)
{
    const int bx = blockIdx.x;
    const int i = bx & (T_-1);
    const int h = bx >> 10;
    const float slope = (h < 8) ? exp2f(-(float)(h+1)) : exp2f(-0.5f * (float)(h-7));
    float* row = sc + ((long long)h*T_ + i) * T_;
    const int n = i + 1;
    const int tid = threadIdx.x;
    __shared__ float sh[8];

    float m = -3.4e38f;
    for (int j = tid; j < n; j += 256)
        m = fmaxf(m, row[j] + slope * (float)(j - i));
    #pragma unroll
    for (int o = 16; o; o >>= 1) m = fmaxf(m, __shfl_xor_sync(0xffffffffu, m, o));
    if ((tid & 31) == 0) sh[tid >> 5] = m;
    __syncthreads();
    float M = sh[0];
    #pragma unroll
    for (int w = 1; w < 8; w++) M = fmaxf(M, sh[w]);
    __syncthreads();

    float s = 0.f;
    for (int j = tid; j < n; j += 256) {
        float e = expf(row[j] + slope * (float)(j - i) - M);
        row[j] = e; s += e;
    }
    #pragma unroll
    for (int o = 16; o; o >>= 1) s += __shfl_xor_sync(0xffffffffu, s, o);
    if ((tid & 31) == 0) sh[tid >> 5] = s;
    __syncthreads();
    float S = 0.f;
    #pragma unroll
    for (int w = 0; w < 8; w++) S += sh[w];
    float inv = 1.f / S;
    for (int j = tid; j < n; j += 256) row[j] *= inv;
    for (int j = n + tid; j < T_; j += 256) row[j] = 0.f;
}

// xt_new[t, i*64+d] = xt + sum_j out_fact[i,j] * y[t, j*64+d]
__global__ void outmix_kernel(const float* __restrict__ xt, const float* __restrict__ of,
                              const float* __restrict__ y, float* __restrict__ o)
{
    int idx = blockIdx.x * 256 + threadIdx.x;      // T*D
    int d = idx & (HD_-1);
    int i = (idx >> 6) % H_;
    int t = idx / D_;
    float s = 0.f;
    #pragma unroll
    for (int j = 0; j < H_; j++)
        s += of[i*H_ + j] * y[(long long)t*D_ + j*HD_ + d];
    o[idx] = xt[idx] + s;
}

// per-(h,t) LayerNorm over HD=64 (one warp per row)
__global__ void dln_kernel(const float* __restrict__ xp, const float* __restrict__ w,
                           const float* __restrict__ b, float* __restrict__ xh)
{
    int bx = blockIdx.x;
    int t = bx & (T_-1);
    int h = bx >> 10;
    int lane = threadIdx.x;
    const float* p = xp + (long long)t*D_ + h*HD_;
    float v0 = p[lane], v1 = p[lane + 32];
    float s = v0 + v1, ss = v0*v0 + v1*v1;
    #pragma unroll
    for (int o = 16; o; o >>= 1) {
        s  += __shfl_xor_sync(0xffffffffu, s, o);
        ss += __shfl_xor_sync(0xffffffffu, ss, o);
    }
    float mu  = s * (1.f / HD_);
    float var = ss * (1.f / HD_) - mu*mu;
    float inv = rsqrtf(var + 1e-5f);
    float* q = xh + (long long)t*D_ + h*HD_;
    q[lane]      = (v0 - mu) * inv * w[h*HD_ + lane]      + b[h*HD_ + lane];
    q[lane + 32] = (v1 - mu) * inv * w[h*HD_ + lane + 32] + b[h*HD_ + lane + 32];
}

// softmax over V=8192, in place (row held in registers: 8 float4 / thread)
__global__ void dict_softmax_kernel(float* __restrict__ wts)
{
    float4* row = reinterpret_cast<float4*>(wts + (long long)blockIdx.x * V_);
    const int tid = threadIdx.x;
    __shared__ float sh[8];
    float4 v[8];
    float m = -3.4e38f;
    #pragma unroll
    for (int i = 0; i < 8; i++) {
        v[i] = row[tid + i*256];
        m = fmaxf(m, fmaxf(fmaxf(v[i].x, v[i].y), fmaxf(v[i].z, v[i].w)));
    }
    #pragma unroll
    for (int o = 16; o; o >>= 1) m = fmaxf(m, __shfl_xor_sync(0xffffffffu, m, o));
    if ((tid & 31) == 0) sh[tid >> 5] = m;
    __syncthreads();
    float M = sh[0];
    #pragma unroll
    for (int w = 1; w < 8; w++) M = fmaxf(M, sh[w]);
    __syncthreads();

    float s = 0.f;
    #pragma unroll
    for (int i = 0; i < 8; i++) {
        v[i].x = expf(v[i].x - M); v[i].y = expf(v[i].y - M);
        v[i].z = expf(v[i].z - M); v[i].w = expf(v[i].w - M);
        s += v[i].x + v[i].y + v[i].z + v[i].w;
    }
    #pragma unroll
    for (int o = 16; o; o >>= 1) s += __shfl_xor_sync(0xffffffffu, s, o);
    if ((tid & 31) == 0) sh[tid >> 5] = s;
    __syncthreads();
    float S = 0.f;
    #pragma unroll
    for (int w = 0; w < 8; w++) S += sh[w];
    float inv = 1.f / S;
    #pragma unroll
    for (int i = 0; i < 8; i++) {
        v[i].x *= inv; v[i].y *= inv; v[i].z *= inv; v[i].w *= inv;
        row[tid + i*256] = v[i];
    }
}

__global__ void add_kernel(const float* __restrict__ a, const float* __restrict__ b,
                           float* __restrict__ o)
{
    int idx = blockIdx.x * 256 + threadIdx.x;
    o[idx] = a[idx] + b[idx];
}

__global__ void loss_partial_kernel(const float* __restrict__ a, const float* __restrict__ b)
{
    double s = 0.0;
    for (int idx = blockIdx.x*256 + threadIdx.x; idx < T_*D_; idx += 256*256) {
        float d = a[idx] - b[idx];
        s += (double)d * (double)d;
    }
    __shared__ double sh[256];
    sh[threadIdx.x] = s;
    __syncthreads();
    for (int o = 128; o; o >>= 1) {
        if (threadIdx.x < o) sh[threadIdx.x] += sh[threadIdx.x + o];
        __syncthreads();
    }
    if (threadIdx.x == 0) g_lossPartial[blockIdx.x] = sh[0];
}

__global__ void loss_final_kernel(float* __restrict__ out)
{
    __shared__ double sh[256];
    sh[threadIdx.x] = g_lossPartial[threadIdx.x];
    __syncthreads();
    for (int o = 128; o; o >>= 1) {
        if (threadIdx.x < o) sh[threadIdx.x] += sh[threadIdx.x + o];
        __syncthreads();
    }
    if (threadIdx.x == 0) out[0] = (float)(sh[0] / (double)(T_*D_));
}

// ---------------------------------------------------------------------------
// Host launcher
// ---------------------------------------------------------------------------
extern "C" void kernel_launch(void* const* d_in, const int* in_sizes, int n_in,
                              void* d_out, int out_size)
{
    (void)in_sizes; (void)n_in; (void)out_size;
    const float* xt       = (const float*)d_in[0];
    const float* xe       = (const float*)d_in[1];
    const float* ln1_w    = (const float*)d_in[2];
    const float* ln1_b    = (const float*)d_in[3];
    const float* qk_w     = (const float*)d_in[4];
    const float* qk_b     = (const float*)d_in[5];
    const float* v_fact   = (const float*)d_in[6];
    const float* out_fact = (const float*)d_in[7];
    const float* ln2_w    = (const float*)d_in[8];
    const float* ln2_b    = (const float*)d_in[9];
    const float* fc_w     = (const float*)d_in[10];
    const float* fc_b     = (const float*)d_in[11];
    const float* proj_w   = (const float*)d_in[12];
    const float* proj_b   = (const float*)d_in[13];
    const float* dln_w    = (const float*)d_in[14];
    const float* dln_b    = (const float*)d_in[15];
    const float* dict_emb = (const float*)d_in[16];

    float* out    = (float*)d_out;
    float* o_xt   = out;
    float* o_xe   = out + OFF_XE;
    float* o_w    = out + OFF_W;
    float* o_loss = out + OFF_LOSS;

    float *p_xnorm, *p_qk, *p_v, *p_vT, *p_sc, *p_y, *p_x2, *p_h,
          *p_xpre, *p_xhat, *p_embT, *p_recon;
    cudaGetSymbolAddress((void**)&p_xnorm, g_xnorm);
    cudaGetSymbolAddress((void**)&p_qk,    g_qk);
    cudaGetSymbolAddress((void**)&p_v,     g_v);
    cudaGetSymbolAddress((void**)&p_vT,    g_vT);
    cudaGetSymbolAddress((void**)&p_sc,    g_scores);
    cudaGetSymbolAddress((void**)&p_y,     g_y);
    cudaGetSymbolAddress((void**)&p_x2,    g_x2);
    cudaGetSymbolAddress((void**)&p_h,     g_h);
    cudaGetSymbolAddress((void**)&p_xpre,  g_xpre);
    cudaGetSymbolAddress((void**)&p_xhat,  g_xhat);
    cudaGetSymbolAddress((void**)&p_embT,  g_embT);
    cudaGetSymbolAddress((void**)&p_recon, g_recon);

    // 1) x_norm = LN(xt + xe)
    ln2in_kernel<<<T_, 256>>>(xt, xe, ln1_w, ln1_b, p_xnorm);

    // 2) qk = x_norm @ qk_w^T + qk_b       [T, 1536]
    gemm_tc<128,128,32,64,64,128><<<dim3(2*D_/128, T_/128, 1), 128>>>(
        p_xnorm, qk_w, p_qk, qk_b, D_, D_, D_, 2*D_, 0,0,0,0, 1.f, 1, 0, 0, 0);

    // 3) v[h,t,d] then vT[h,d,t]
    vmix_kernel<<<H_*T_*HD_/256, 256>>>(xt, v_fact, p_v);
    transpose_kernel<<<dim3(HD_/32, T_/32, H_), dim3(32,8)>>>(p_v, p_vT, T_, HD_);

    // 4) scores[h] = 0.125 * q[h] @ k[h]^T   (causal blocks only)
    gemm_tc<128,128,32,64,64,128><<<dim3(T_/128, T_/128, H_), 128>>>(
        p_qk, p_qk + D_, p_sc, nullptr, HD_, 2*D_, 2*D_, T_,
        64, 64, (long long)T_*T_, 0, 0.125f, 0, 1, 0, 0);

    // 5) causal ALiBi softmax in place
    attn_softmax_kernel<<<H_*T_, 256>>>(p_sc);

    // 6) y[h] = probs[h] @ v[h]  -> g_y[t, h*64+d]   (K capped at diagonal)
    gemm_tc<64,64,32,32,32,128><<<dim3(HD_/64, T_/64, H_), 128>>>(
        p_sc, p_vT, p_y, nullptr, T_, T_, T_, D_,
        (long long)T_*T_, (long long)HD_*T_, 64, 0, 1.f, 0, 0, 1, 0);

    // 7) xt_new = xt + out_fact-mix(y)   (output region 0)
    outmix_kernel<<<T_*D_/256, 256>>>(xt, out_fact, p_y, o_xt);

    // 8) x2 = LN(xt_new + xe)
    ln2in_kernel<<<T_, 256>>>(o_xt, xe, ln2_w, ln2_b, p_x2);

    // 9) h = gelu(x2 @ fc_w^T + fc_b)   [T, 36864]   -- dominant GEMM
    //    swapxy=1: grid.x = M blocks so same-B blocks run adjacently (B streamed once)
    gemm_tc<128,128,32,64,64,128><<<dim3(T_/128, H_*FF_/128, 1), 128>>>(
        p_x2, fc_w, p_h, fc_b, D_, D_, D_, H_*FF_, 0,0,0,0, 1.f, 2, 0, 0, 1);

    // 10) xpre[h] = h[h] @ proj_w[h]^T + proj_b[h]  -> [t, h*64+d]
    gemm_tc<64,64,32,32,32,128><<<dim3(HD_/64, T_/64, H_), 128>>>(
        p_h, proj_w, p_xpre, proj_b, FF_, H_*FF_, FF_, D_,
        FF_, (long long)HD_*FF_, 64, HD_, 1.f, 1, 0, 0, 0);

    // 11) x_hat = per-head LN(xpre)
    dln_kernel<<<H_*T_, 32>>>(p_xpre, dln_w, dln_b, p_xhat);

    // 12) embT[h] = dict_emb[h]^T    [HD, V]
    transpose_kernel<<<dim3(HD_/32, V_/32, H_), dim3(32,8)>>>(dict_emb, p_embT, V_, HD_);

    // 13) dict_logits[h] = x_hat[h] @ dict_emb[h]^T  -> output region
    gemm_tc<128,128,32,64,64,128><<<dim3(T_/128, V_/128, H_), 128>>>(
        p_xhat, dict_emb, o_w, nullptr, HD_, D_, HD_, V_,
        64, (long long)V_*HD_, (long long)T_*V_, 0, 1.f, 0, 0, 0, 1);

    // 14) dict_weights = softmax over V (in place in output)
    dict_softmax_kernel<<<H_*T_, 256>>>(o_w);

    // 15) x_recon[h] = weights[h] @ dict_emb[h]  -> [t, h*64+d]
    gemm_tc<64,64,32,32,32,128><<<dim3(HD_/64, T_/64, H_), 128>>>(
        o_w, p_embT, p_recon, nullptr, V_, V_, V_, D_,
        (long long)T_*V_, (long long)HD_*V_, 64, 0, 1.f, 0, 0, 0, 0);

    // 16) xe_new = xe + x_recon
    add_kernel<<<T_*D_/256, 256>>>(xe, p_recon, o_xe);

    // 17) dict_loss = mean((x_hat - x_recon)^2)
    loss_partial_kernel<<<256, 256>>>(p_xhat, p_recon);
    loss_final_kernel<<<1, 256>>>(o_loss);
}

// round 11
// speedup vs baseline: 2.8058x; 1.1480x over previous
#include <cuda_runtime.h>
#include <math.h>

// ---------------------------------------------------------------------------
// Problem constants
// ---------------------------------------------------------------------------
#define T_  1024
#define D_  768
#define H_  12
#define FF_ 3072
#define V_  8192
#define HD_ 64

// output layout: xt_new [T*D] | xe_new [T*D] | dict_weights [H*T*V] | loss [1]
#define OFF_XE   (T_*D_)
#define OFF_W    (2*T_*D_)
#define OFF_LOSS (2*T_*D_ + H_*T_*V_)

// ---------------------------------------------------------------------------
// Device scratch (allocation-free: __device__ globals)
// ---------------------------------------------------------------------------
__device__ __align__(16) float g_xnorm[T_*D_];
__device__ __align__(16) float g_qk[T_*2*D_];
__device__ __align__(16) float g_v[H_*T_*HD_];
__device__ __align__(16) float g_vT[H_*HD_*T_];
__device__ __align__(16) float g_scores[H_*T_*T_];          // 50 MB
__device__ __align__(16) float g_y[T_*D_];
__device__ __align__(16) float g_x2[T_*D_];
__device__ __align__(16) float g_h[T_*H_*FF_];              // 151 MB
__device__ __align__(16) float g_xpre[T_*D_];
__device__ __align__(16) float g_xhat[T_*D_];
__device__ __align__(16) float g_embT[H_*HD_*V_];           // 25 MB
__device__ __align__(16) float g_recon[T_*D_];
__device__ double g_lossPartial[256];

// ---------------------------------------------------------------------------
// Helpers
// ---------------------------------------------------------------------------
__device__ __forceinline__ float gelu_exact(float x) {
    return 0.5f * x * (1.0f + erff(x * 0.70710678118654752f));
}

__device__ __forceinline__ void cp_async16(void* s, const void* g) {
    unsigned sa = (unsigned)__cvta_generic_to_shared(s);
    asm volatile("cp.async.cg.shared.global [%0], [%1], 16;\n" :: "r"(sa), "l"(g));
}
__device__ __forceinline__ void cp_commit() {
    asm volatile("cp.async.commit_group;\n");
}
template<int N>
__device__ __forceinline__ void cp_wait() {
    asm volatile("cp.async.wait_group %0;\n" :: "n"(N));
}

// ---------------------------------------------------------------------------
// Tensor-core NT GEMM (tf32 mma.sync m16n8k8), cp.async 2-stage pipeline.
//   C[m,n] = alpha * sum_k A[m,k]*B[n,k]   (+bias, +gelu) ; batched over z
// A: [M,K] rows lda ; B: [N,K] rows ldb ; C: [M,N] rows ldc.
// smem holds raw fp32; HW truncates mantissa for tf32 mma operands.
// mode: 0 = alpha only, 1 = +bias, 2 = +bias then exact gelu
// causal: skip blocks fully above diagonal ; kcap: Keff = min(K, m0+BM)
// swapxy: m-block from blockIdx.x (groups same-B blocks adjacently)
// Requires: M%BM==0, N%BN==0, Keff%BK==0.
// ---------------------------------------------------------------------------
template<int BM, int BN, int BK, int WM, int WN, int THREADS>
__global__ void __launch_bounds__(THREADS)
gemm_tc(const float* __restrict__ A, const float* __restrict__ B,
        float* __restrict__ C, const float* __restrict__ bias,
        int K, int lda, int ldb, int ldc,
        long long sA, long long sB, long long sC, long long sBias,
        float alpha, int mode, int causal, int kcap, int swapxy)
{
    constexpr int NWN = BN / WN;          // warps along N
    constexpr int TM  = WM / 16;          // mma tiles per warp along M
    constexpr int TN  = WN / 8;           // mma tiles per warp along N
    constexpr int LK  = BK + 4;           // smem row stride (words) -> conflict-free
    constexpr int LA  = BM * (BK/4) / THREADS;   // float4 loads per thread (A)
    constexpr int LB  = BN * (BK/4) / THREADS;

    const int bx = blockIdx.x, by = blockIdx.y;
    const int m0 = (swapxy ? bx : by) * BM;
    const int n0 = (swapxy ? by : bx) * BN;
    if (causal && n0 > m0 + BM - 1) return;

    __shared__ __align__(16) float As[2][BM][LK];
    __shared__ __align__(16) float Bs[2][BN][LK];

    const int bz = blockIdx.z;
    A += bz * sA;  B += bz * sB;  C += bz * sC;
    if (mode >= 1) bias += bz * sBias;

    const int tid  = threadIdx.x;
    const int lane = tid & 31;
    const int warp = tid >> 5;
    const int gid  = lane >> 2;           // 0..7
    const int t4   = lane & 3;            // 0..3
    const int wm   = warp / NWN;
    const int wn   = warp % NWN;

    float acc[TM][TN][4];
    #pragma unroll
    for (int i = 0; i < TM; i++)
        #pragma unroll
        for (int j = 0; j < TN; j++) {
            acc[i][j][0] = 0.f; acc[i][j][1] = 0.f;
            acc[i][j][2] = 0.f; acc[i][j][3] = 0.f;
        }

    int Keff = K;
    if (kcap) { int ke = m0 + BM; if (ke < K) Keff = ke; }
    const int niter = Keff / BK;

    auto load_stage = [&](int st, int k0) {
        #pragma unroll
        for (int i = 0; i < LA; i++) {
            int l = tid + i * THREADS;
            int r = l / (BK/4), q = (l % (BK/4)) * 4;
            cp_async16(&As[st][r][q], A + (long long)(m0 + r) * lda + k0 + q);
        }
        #pragma unroll
        for (int i = 0; i < LB; i++) {
            int l = tid + i * THREADS;
            int r = l / (BK/4), q = (l % (BK/4)) * 4;
            cp_async16(&Bs[st][r][q], B + (long long)(n0 + r) * ldb + k0 + q);
        }
    };

    // prologue: two stages in flight
    load_stage(0, 0);
    cp_commit();
    if (niter > 1) load_stage(1, BK);
    cp_commit();

    for (int it = 0; it < niter; it++) {
        cp_wait<1>();
        __syncthreads();

        const int st = it & 1;
        #pragma unroll
        for (int kk = 0; kk < BK; kk += 8) {
            unsigned a[TM][4], b[TN][2];
            #pragma unroll
            for (int i = 0; i < TM; i++) {
                int r = wm * WM + i * 16 + gid;
                a[i][0] = __float_as_uint(As[st][r    ][kk + t4]);
                a[i][1] = __float_as_uint(As[st][r + 8][kk + t4]);
                a[i][2] = __float_as_uint(As[st][r    ][kk + t4 + 4]);
                a[i][3] = __float_as_uint(As[st][r + 8][kk + t4 + 4]);
            }
            #pragma unroll
            for (int j = 0; j < TN; j++) {
                int c = wn * WN + j * 8 + gid;
                b[j][0] = __float_as_uint(Bs[st][c][kk + t4]);
                b[j][1] = __float_as_uint(Bs[st][c][kk + t4 + 4]);
            }
            #pragma unroll
            for (int i = 0; i < TM; i++)
                #pragma unroll
                for (int j = 0; j < TN; j++) {
                    asm volatile(
                        "mma.sync.aligned.m16n8k8.row.col.f32.tf32.tf32.f32 "
                        "{%0,%1,%2,%3}, {%4,%5,%6,%7}, {%8,%9}, {%0,%1,%2,%3};\n"
                        : "+f"(acc[i][j][0]), "+f"(acc[i][j][1]),
                          "+f"(acc[i][j][2]), "+f"(acc[i][j][3])
                        : "r"(a[i][0]), "r"(a[i][1]), "r"(a[i][2]), "r"(a[i][3]),
                          "r"(b[j][0]), "r"(b[j][1]));
                }
        }
        __syncthreads();

        if (it + 2 < niter) load_stage(st, (it + 2) * BK);
        cp_commit();   // commit (possibly empty) to keep group count uniform
    }

    // ---- epilogue ----
    #pragma unroll
    for (int i = 0; i < TM; i++) {
        const int m = m0 + wm * WM + i * 16 + gid;
        #pragma unroll
        for (int j = 0; j < TN; j++) {
            const int n = n0 + wn * WN + j * 8 + t4 * 2;
            float c0 = acc[i][j][0] * alpha, c1 = acc[i][j][1] * alpha;
            float c2 = acc[i][j][2] * alpha, c3 = acc[i][j][3] * alpha;
            if (mode >= 1) {
                float b0 = bias[n], b1 = bias[n + 1];
                c0 += b0; c1 += b1; c2 += b0; c3 += b1;
            }
            if (mode == 2) {
                c0 = gelu_exact(c0); c1 = gelu_exact(c1);
                c2 = gelu_exact(c2); c3 = gelu_exact(c3);
            }
            *reinterpret_cast<float2*>(C + (long long)m       * ldc + n) = make_float2(c0, c1);
            *reinterpret_cast<float2*>(C + (long long)(m + 8) * ldc + n) = make_float2(c2, c3);
        }
    }
}

// ---------------------------------------------------------------------------
// LayerNorm over D=768 of (a + b)
// ---------------------------------------------------------------------------
__global__ void ln2in_kernel(const float* __restrict__ a, const float* __restrict__ b,
                             const float* __restrict__ w, const float* __restrict__ bb,
                             float* __restrict__ out)
{
    const int t = blockIdx.x;
    const int tid = threadIdx.x;
    const float* pa = a + (long long)t * D_;
    const float* pb = b + (long long)t * D_;
    float x[3];
    float s = 0.f, ss = 0.f;
    #pragma unroll
    for (int i = 0; i < 3; i++) {
        int d = tid + i*256;
        float v = pa[d] + pb[d];
        x[i] = v; s += v; ss += v*v;
    }
    #pragma unroll
    for (int o = 16; o; o >>= 1) {
        s  += __shfl_xor_sync(0xffffffffu, s, o);
        ss += __shfl_xor_sync(0xffffffffu, ss, o);
    }
    __shared__ float rs[8], rss[8];
    __shared__ float s_mu, s_inv;
    if ((tid & 31) == 0) { rs[tid >> 5] = s; rss[tid >> 5] = ss; }
    __syncthreads();
    if (tid == 0) {
        float S = 0.f, SS = 0.f;
        #pragma unroll
        for (int i = 0; i < 8; i++) { S += rs[i]; SS += rss[i]; }
        float mu  = S * (1.f / D_);
        float var = SS * (1.f / D_) - mu*mu;
        s_mu = mu;
        s_inv = rsqrtf(var + 1e-5f);
    }
    __syncthreads();
    float mu = s_mu, inv = s_inv;
    #pragma unroll
    for (int i = 0; i < 3; i++) {
        int d = tid + i*256;
        out[(long long)t*D_ + d] = (x[i] - mu) * inv * w[d] + bb[d];
    }
}

// v[h,t,d] = sum_j v_fact[h,j] * xt[t, j*64+d]
__global__ void vmix_kernel(const float* __restrict__ xt, const float* __restrict__ vf,
                            float* __restrict__ v)
{
    int idx = blockIdx.x * 256 + threadIdx.x;      // H*T*HD
    int d = idx & (HD_-1);
    int t = (idx >> 6) & (T_-1);
    int h = idx >> 16;
    float s = 0.f;
    #pragma unroll
    for (int j = 0; j < H_; j++)
        s += vf[h*H_ + j] * xt[(long long)t*D_ + j*HD_ + d];
    v[idx] = s;
}

// batched transpose in[b][R][C] -> out[b][C][R]   (R,C multiples of 32)
__global__ void transpose_kernel(const float* __restrict__ in, float* __restrict__ out,
                                 int R, int Cc)
{
    __shared__ float tile[32][33];
    const long long boff = (long long)blockIdx.z * R * Cc;
    in += boff; out += boff;
    int c0 = blockIdx.x * 32, r0 = blockIdx.y * 32;
    int x = threadIdx.x, y = threadIdx.y;
    #pragma unroll
    for (int i = 0; i < 32; i += 8)
        tile[y+i][x] = in[(long long)(r0 + y + i) * Cc + c0 + x];
    __syncthreads();
    #pragma unroll
    for (int i = 0; i < 32; i += 8)
        out[(long long)(c0 + y + i) * R + r0 + x] = tile[x][y+i];
}

// causal ALiBi softmax, in place on scores[h][i][:]
__global__ void attn_softmax_kernel(float* __restrict__ sc)
{
    const int bx = blockIdx.x;
    const int i = bx & (T_-1);
    const int h = bx >> 10;
    const float slope = (h < 8) ? exp2f(-(float)(h+1)) : exp2f(-0.5f * (float)(h-7));
    float* row = sc + ((long long)h*T_ + i) * T_;
    const int n = i + 1;
    const int tid = threadIdx.x;
    __shared__ float sh[8];

    float m = -3.4e38f;
    for (int j = tid; j < n; j += 256)
        m = fmaxf(m, row[j] + slope * (float)(j - i));
    #pragma unroll
    for (int o = 16; o; o >>= 1) m = fmaxf(m, __shfl_xor_sync(0xffffffffu, m, o));
    if ((tid & 31) == 0) sh[tid >> 5] = m;
    __syncthreads();
    float M = sh[0];
    #pragma unroll
    for (int w = 1; w < 8; w++) M = fmaxf(M, sh[w]);
    __syncthreads();

    float s = 0.f;
    for (int j = tid; j < n; j += 256) {
        float e = expf(row[j] + slope * (float)(j - i) - M);
        row[j] = e; s += e;
    }
    #pragma unroll
    for (int o = 16; o; o >>= 1) s += __shfl_xor_sync(0xffffffffu, s, o);
    if ((tid & 31) == 0) sh[tid >> 5] = s;
    __syncthreads();
    float S = 0.f;
    #pragma unroll
    for (int w = 0; w < 8; w++) S += sh[w];
    float inv = 1.f / S;
    for (int j = tid; j < n; j += 256) row[j] *= inv;
    for (int j = n + tid; j < T_; j += 256) row[j] = 0.f;
}

// xt_new[t, i*64+d] = xt + sum_j out_fact[i,j] * y[t, j*64+d]
__global__ void outmix_kernel(const float* __restrict__ xt, const float* __restrict__ of,
                              const float* __restrict__ y, float* __restrict__ o)
{
    int idx = blockIdx.x * 256 + threadIdx.x;      // T*D
    int d = idx & (HD_-1);
    int i = (idx >> 6) % H_;
    int t = idx / D_;
    float s = 0.f;
    #pragma unroll
    for (int j = 0; j < H_; j++)
        s += of[i*H_ + j] * y[(long long)t*D_ + j*HD_ + d];
    o[idx] = xt[idx] + s;
}

// per-(h,t) LayerNorm over HD=64 (one warp per row)
__global__ void dln_kernel(const float* __restrict__ xp, const float* __restrict__ w,
                           const float* __restrict__ b, float* __restrict__ xh)
{
    int bx = blockIdx.x;
    int t = bx & (T_-1);
    int h = bx >> 10;
    int lane = threadIdx.x;
    const float* p = xp + (long long)t*D_ + h*HD_;
    float v0 = p[lane], v1 = p[lane + 32];
    float s = v0 + v1, ss = v0*v0 + v1*v1;
    #pragma unroll
    for (int o = 16; o; o >>= 1) {
        s  += __shfl_xor_sync(0xffffffffu, s, o);
        ss += __shfl_xor_sync(0xffffffffu, ss, o);
    }
    float mu  = s * (1.f / HD_);
    float var = ss * (1.f / HD_) - mu*mu;
    float inv = rsqrtf(var + 1e-5f);
    float* q = xh + (long long)t*D_ + h*HD_;
    q[lane]      = (v0 - mu) * inv * w[h*HD_ + lane]      + b[h*HD_ + lane];
    q[lane + 32] = (v1 - mu) * inv * w[h*HD_ + lane + 32] + b[h*HD_ + lane + 32];
}

// softmax over V=8192, in place (row held in registers: 8 float4 / thread)
__global__ void dict_softmax_kernel(float* __restrict__ wts)
{
    float4* row = reinterpret_cast<float4*>(wts + (long long)blockIdx.x * V_);
    const int tid = threadIdx.x;
    __shared__ float sh[8];
    float4 v[8];
    float m = -3.4e38f;
    #pragma unroll
    for (int i = 0; i < 8; i++) {
        v[i] = row[tid + i*256];
        m = fmaxf(m, fmaxf(fmaxf(v[i].x, v[i].y), fmaxf(v[i].z, v[i].w)));
    }
    #pragma unroll
    for (int o = 16; o; o >>= 1) m = fmaxf(m, __shfl_xor_sync(0xffffffffu, m, o));
    if ((tid & 31) == 0) sh[tid >> 5] = m;
    __syncthreads();
    float M = sh[0];
    #pragma unroll
    for (int w = 1; w < 8; w++) M = fmaxf(M, sh[w]);
    __syncthreads();

    float s = 0.f;
    #pragma unroll
    for (int i = 0; i < 8; i++) {
        v[i].x = expf(v[i].x - M); v[i].y = expf(v[i].y - M);
        v[i].z = expf(v[i].z - M); v[i].w = expf(v[i].w - M);
        s += v[i].x + v[i].y + v[i].z + v[i].w;
    }
    #pragma unroll
    for (int o = 16; o; o >>= 1) s += __shfl_xor_sync(0xffffffffu, s, o);
    if ((tid & 31) == 0) sh[tid >> 5] = s;
    __syncthreads();
    float S = 0.f;
    #pragma unroll
    for (int w = 0; w < 8; w++) S += sh[w];
    float inv = 1.f / S;
    #pragma unroll
    for (int i = 0; i < 8; i++) {
        v[i].x *= inv; v[i].y *= inv; v[i].z *= inv; v[i].w *= inv;
        row[tid + i*256] = v[i];
    }
}

__global__ void add_kernel(const float* __restrict__ a, const float* __restrict__ b,
                           float* __restrict__ o)
{
    int idx = blockIdx.x * 256 + threadIdx.x;
    o[idx] = a[idx] + b[idx];
}

__global__ void loss_partial_kernel(const float* __restrict__ a, const float* __restrict__ b)
{
    double s = 0.0;
    for (int idx = blockIdx.x*256 + threadIdx.x; idx < T_*D_; idx += 256*256) {
        float d = a[idx] - b[idx];
        s += (double)d * (double)d;
    }
    __shared__ double sh[256];
    sh[threadIdx.x] = s;
    __syncthreads();
    for (int o = 128; o; o >>= 1) {
        if (threadIdx.x < o) sh[threadIdx.x] += sh[threadIdx.x + o];
        __syncthreads();
    }
    if (threadIdx.x == 0) g_lossPartial[blockIdx.x] = sh[0];
}

__global__ void loss_final_kernel(float* __restrict__ out)
{
    __shared__ double sh[256];
    sh[threadIdx.x] = g_lossPartial[threadIdx.x];
    __syncthreads();
    for (int o = 128; o; o >>= 1) {
        if (threadIdx.x < o) sh[threadIdx.x] += sh[threadIdx.x + o];
        __syncthreads();
    }
    if (threadIdx.x == 0) out[0] = (float)(sh[0] / (double)(T_*D_));
}

// ---------------------------------------------------------------------------
// Host launcher
// ---------------------------------------------------------------------------
extern "C" void kernel_launch(void* const* d_in, const int* in_sizes, int n_in,
                              void* d_out, int out_size)
{
    (void)in_sizes; (void)n_in; (void)out_size;
    const float* xt       = (const float*)d_in[0];
    const float* xe       = (const float*)d_in[1];
    const float* ln1_w    = (const float*)d_in[2];
    const float* ln1_b    = (const float*)d_in[3];
    const float* qk_w     = (const float*)d_in[4];
    const float* qk_b     = (const float*)d_in[5];
    const float* v_fact   = (const float*)d_in[6];
    const float* out_fact = (const float*)d_in[7];
    const float* ln2_w    = (const float*)d_in[8];
    const float* ln2_b    = (const float*)d_in[9];
    const float* fc_w     = (const float*)d_in[10];
    const float* fc_b     = (const float*)d_in[11];
    const float* proj_w   = (const float*)d_in[12];
    const float* proj_b   = (const float*)d_in[13];
    const float* dln_w    = (const float*)d_in[14];
    const float* dln_b    = (const float*)d_in[15];
    const float* dict_emb = (const float*)d_in[16];

    float* out    = (float*)d_out;
    float* o_xt   = out;
    float* o_xe   = out + OFF_XE;
    float* o_w    = out + OFF_W;
    float* o_loss = out + OFF_LOSS;

    float *p_xnorm, *p_qk, *p_v, *p_vT, *p_sc, *p_y, *p_x2, *p_h,
          *p_xpre, *p_xhat, *p_embT, *p_recon;
    cudaGetSymbolAddress((void**)&p_xnorm, g_xnorm);
    cudaGetSymbolAddress((void**)&p_qk,    g_qk);
    cudaGetSymbolAddress((void**)&p_v,     g_v);
    cudaGetSymbolAddress((void**)&p_vT,    g_vT);
    cudaGetSymbolAddress((void**)&p_sc,    g_scores);
    cudaGetSymbolAddress((void**)&p_y,     g_y);
    cudaGetSymbolAddress((void**)&p_x2,    g_x2);
    cudaGetSymbolAddress((void**)&p_h,     g_h);
    cudaGetSymbolAddress((void**)&p_xpre,  g_xpre);
    cudaGetSymbolAddress((void**)&p_xhat,  g_xhat);
    cudaGetSymbolAddress((void**)&p_embT,  g_embT);
    cudaGetSymbolAddress((void**)&p_recon, g_recon);

    // 1) x_norm = LN(xt + xe)
    ln2in_kernel<<<T_, 256>>>(xt, xe, ln1_w, ln1_b, p_xnorm);

    // 2) qk = x_norm @ qk_w^T + qk_b       [T, 1536]
    gemm_tc<128,128,16,64,32,256><<<dim3(2*D_/128, T_/128, 1), 256>>>(
        p_xnorm, qk_w, p_qk, qk_b, D_, D_, D_, 2*D_, 0,0,0,0, 1.f, 1, 0, 0, 0);

    // 3) v[h,t,d] then vT[h,d,t]
    vmix_kernel<<<H_*T_*HD_/256, 256>>>(xt, v_fact, p_v);
    transpose_kernel<<<dim3(HD_/32, T_/32, H_), dim3(32,8)>>>(p_v, p_vT, T_, HD_);

    // 4) scores[h] = 0.125 * q[h] @ k[h]^T   (causal blocks only)
    gemm_tc<128,128,16,64,32,256><<<dim3(T_/128, T_/128, H_), 256>>>(
        p_qk, p_qk + D_, p_sc, nullptr, HD_, 2*D_, 2*D_, T_,
        64, 64, (long long)T_*T_, 0, 0.125f, 0, 1, 0, 0);

    // 5) causal ALiBi softmax in place
    attn_softmax_kernel<<<H_*T_, 256>>>(p_sc);

    // 6) y[h] = probs[h] @ v[h]  -> g_y[t, h*64+d]   (K capped at diagonal)
    gemm_tc<64,64,16,32,32,128><<<dim3(HD_/64, T_/64, H_), 128>>>(
        p_sc, p_vT, p_y, nullptr, T_, T_, T_, D_,
        (long long)T_*T_, (long long)HD_*T_, 64, 0, 1.f, 0, 0, 1, 0);

    // 7) xt_new = xt + out_fact-mix(y)   (output region 0)
    outmix_kernel<<<T_*D_/256, 256>>>(xt, out_fact, p_y, o_xt);

    // 8) x2 = LN(xt_new + xe)
    ln2in_kernel<<<T_, 256>>>(o_xt, xe, ln2_w, ln2_b, p_x2);

    // 9) h = gelu(x2 @ fc_w^T + fc_b)   [T, 36864]   -- dominant GEMM
    //    swapxy=1: grid.x = M blocks so same-B blocks run adjacently
    gemm_tc<128,128,16,64,32,256><<<dim3(T_/128, H_*FF_/128, 1), 256>>>(
        p_x2, fc_w, p_h, fc_b, D_, D_, D_, H_*FF_, 0,0,0,0, 1.f, 2, 0, 0, 1);

    // 10) xpre[h] = h[h] @ proj_w[h]^T + proj_b[h]  -> [t, h*64+d]
    gemm_tc<64,64,16,32,32,128><<<dim3(HD_/64, T_/64, H_), 128>>>(
        p_h, proj_w, p_xpre, proj_b, FF_, H_*FF_, FF_, D_,
        FF_, (long long)HD_*FF_, 64, HD_, 1.f, 1, 0, 0, 0);

    // 11) x_hat = per-head LN(xpre)
    dln_kernel<<<H_*T_, 32>>>(p_xpre, dln_w, dln_b, p_xhat);

    // 12) embT[h] = dict_emb[h]^T    [HD, V]
    transpose_kernel<<<dim3(HD_/32, V_/32, H_), dim3(32,8)>>>(dict_emb, p_embT, V_, HD_);

    // 13) dict_logits[h] = x_hat[h] @ dict_emb[h]^T  -> output region
    gemm_tc<128,128,16,64,32,256><<<dim3(T_/128, V_/128, H_), 256>>>(
        p_xhat, dict_emb, o_w, nullptr, HD_, D_, HD_, V_,
        64, (long long)V_*HD_, (long long)T_*V_, 0, 1.f, 0, 0, 0, 1);

    // 14) dict_weights = softmax over V (in place in output)
    dict_softmax_kernel<<<H_*T_, 256>>>(o_w);

    // 15) x_recon[h] = weights[h] @ dict_emb[h]  -> [t, h*64+d]
    gemm_tc<64,64,16,32,32,128><<<dim3(HD_/64, T_/64, H_), 128>>>(
        o_w, p_embT, p_recon, nullptr, V_, V_, V_, D_,
        (long long)T_*V_, (long long)HD_*V_, 64, 0, 1.f, 0, 0, 0, 0);

    // 16) xe_new = xe + x_recon
    add_kernel<<<T_*D_/256, 256>>>(xe, p_recon, o_xe);

    // 17) dict_loss = mean((x_hat - x_recon)^2)
    loss_partial_kernel<<<256, 256>>>(p_xhat, p_recon);
    loss_final_kernel<<<1, 256>>>(o_loss);
}